// round 5
// baseline (speedup 1.0000x reference)
#include <cuda_runtime.h>
#include <cuda_bf16.h>
#include <math.h>
#include <stdint.h>

// Problem dims
#define BB 16
#define TT 128
#define EE 512
#define HH 1024
#define VV 32000
#define CLL 49
#define CDD 2048
#define BT (BB*TT)            // 2048
#define G4 (4*HH)             // 4096

typedef unsigned long long u64;

// ---- packed fp32x2 helpers (FFMA2 path) -----------------------------------
__device__ __forceinline__ u64 pk2(float lo, float hi){
    u64 r;
    asm("mov.b64 %0, {%1, %2};" : "=l"(r) : "f"(lo), "f"(hi));
    return r;
}
__device__ __forceinline__ void fma2(u64& d, u64 a, u64 b){
    asm("fma.rn.f32x2 %0, %1, %2, %3;" : "=l"(d) : "l"(a), "l"(b), "l"(d));
}
__device__ __forceinline__ float2 up2(u64 v){
    float2 r;
    asm("mov.b64 {%0, %1}, %2;" : "=f"(r.x), "=f"(r.y) : "l"(v));
    return r;
}

// ---- tf32 helpers ----------------------------------------------------------
__device__ __forceinline__ void split_tf(float x, uint32_t& hi, uint32_t& lo){
    asm("cvt.rna.tf32.f32 %0, %1;" : "=r"(hi) : "f"(x));
    float r = x - __uint_as_float(hi);
    asm("cvt.rna.tf32.f32 %0, %1;" : "=r"(lo) : "f"(r));
}
__device__ __forceinline__ void mma_tf32(float* c, const uint32_t* a, uint32_t b0, uint32_t b1){
    asm volatile("mma.sync.aligned.m16n8k8.row.col.f32.tf32.tf32.f32 "
        "{%0,%1,%2,%3}, {%4,%5,%6,%7}, {%8,%9}, {%0,%1,%2,%3};"
        : "+f"(c[0]), "+f"(c[1]), "+f"(c[2]), "+f"(c[3])
        : "r"(a[0]), "r"(a[1]), "r"(a[2]), "r"(a[3]), "r"(b0), "r"(b1));
}

// ---------------- scratch (device globals; no allocation allowed) ----------
__device__ float g_xemb[BT*EE];          // 2048x512
__device__ float g_xg[(size_t)BT*G4];    // 2048x4096
__device__ float g_bias4h[G4];
__device__ float g_h[2][BB*HH];
__device__ float g_c[BB*HH];
__device__ float g_hs[(size_t)BT*HH];    // 2048x1024
__device__ float g_partial[8*BB*G4];     // [kc][b][row]
__device__ float g_q[(size_t)BT*HH];
__device__ float g_k[(size_t)BB*CLL*HH];
__device__ float g_v[(size_t)BB*CLL*HH];
__device__ float g_att[(size_t)BT*HH];
__device__ float g_cat[(size_t)BT*2*HH]; // 2048x2048
__device__ float g_merged[(size_t)BT*HH];

// ---------------- small kernels -------------------------------------------
__global__ void bias_comb_k(const float* __restrict__ a, const float* __restrict__ b){
    int i = blockIdx.x*256 + threadIdx.x;
    if (i < G4) g_bias4h[i] = a[i] + b[i];
}

__global__ void embed_k(const int* __restrict__ words, const float* __restrict__ emb){
    int row = blockIdx.x;                 // 0..2047
    int w = words[row];
    const float4* src = (const float4*)(emb + (size_t)w*EE);
    float4* dst = (float4*)(g_xemb + (size_t)row*EE);
    dst[threadIdx.x] = src[threadIdx.x];  // 128 threads * float4 = 512 floats
}

// ---------------- tensor-core GEMM (3xTF32): C = A[M,K] @ B[N,K]^T + bias --
// BM=BN=128, BK=16, 256 threads (8 warps, 2Mx4N), warp tile 64x32,
// mma.sync.m16n8k8 tf32 with hi/lo error compensation (fp32-grade accuracy).
// Grid: (M-tiles, N-tiles) -> consecutive blocks share the same B n-tile,
// so B (the large operand, e.g. Wp = 131 MB) gets wave-level L2 reuse.
// Requires: K%16==0, N%128==0. M guarded. ACT: 0=none, 1=tanh
template<int ACT>
__global__ void __launch_bounds__(256) gemm_tf32(
    const float* __restrict__ A, const float* __restrict__ B,
    const float* __restrict__ bias, float* __restrict__ C,
    int M, int N, int K)
{
    __shared__ float As[128][20];   // stride 20 floats = 80B (16B aligned)
    __shared__ float Bs[128][20];
    const int m0 = blockIdx.x*128, n0 = blockIdx.y*128;
    const int t = threadIdx.x;
    const int warp = t >> 5, lane = t & 31;
    const int wm = warp & 1;        // 0..1 : 64-row half
    const int wn = warp >> 1;       // 0..3 : 32-col quarter
    const int lr = lane >> 2, lc = lane & 3;

    // global->smem load coords: 2 rows per thread (r0, r0+64), 4 floats each
    const int r0 = t >> 2, c4 = (t & 3)*4;
    const bool av0 = (m0 + r0) < M;
    const bool av1 = (m0 + 64 + r0) < M;
    const float* Ap0 = A + (size_t)(m0 + r0)*K + c4;
    const float* Ap1 = A + (size_t)(m0 + 64 + r0)*K + c4;
    const float* Bp0 = B + (size_t)(n0 + r0)*K + c4;
    const float* Bp1 = B + (size_t)(n0 + 64 + r0)*K + c4;

    float acc[4][4][4];             // [mfrag][nfrag][reg]
#pragma unroll
    for (int i=0;i<4;i++)
#pragma unroll
        for (int j=0;j<4;j++)
#pragma unroll
            for (int r=0;r<4;r++) acc[i][j][r] = 0.f;

    const int nk = K >> 4;
    const float4 z4 = make_float4(0.f,0.f,0.f,0.f);
    float4 a0v = av0 ? *(const float4*)Ap0 : z4;
    float4 a1v = av1 ? *(const float4*)Ap1 : z4;
    float4 b0v = *(const float4*)Bp0;
    float4 b1v = *(const float4*)Bp1;

    for (int kt=0; kt<nk; kt++){
        *(float4*)&As[r0][c4]      = a0v;
        *(float4*)&As[64 + r0][c4] = a1v;
        *(float4*)&Bs[r0][c4]      = b0v;
        *(float4*)&Bs[64 + r0][c4] = b1v;
        __syncthreads();

        if (kt + 1 < nk){
            Ap0 += 16; Ap1 += 16; Bp0 += 16; Bp1 += 16;
            a0v = av0 ? *(const float4*)Ap0 : z4;
            a1v = av1 ? *(const float4*)Ap1 : z4;
            b0v = *(const float4*)Bp0;
            b1v = *(const float4*)Bp1;
        }

#pragma unroll
        for (int s=0; s<2; s++){
            const int k0 = s*8;
            // A fragments (hi/lo)
            uint32_t ah[4][4], al[4][4];
#pragma unroll
            for (int mf=0; mf<4; mf++){
                const int mr = wm*64 + mf*16 + lr;
                split_tf(As[mr  ][k0+lc  ], ah[mf][0], al[mf][0]);
                split_tf(As[mr+8][k0+lc  ], ah[mf][1], al[mf][1]);
                split_tf(As[mr  ][k0+lc+4], ah[mf][2], al[mf][2]);
                split_tf(As[mr+8][k0+lc+4], ah[mf][3], al[mf][3]);
            }
#pragma unroll
            for (int nf=0; nf<4; nf++){
                const int nr = wn*32 + nf*8 + lr;
                uint32_t bh0, bl0, bh1, bl1;
                split_tf(Bs[nr][k0+lc  ], bh0, bl0);
                split_tf(Bs[nr][k0+lc+4], bh1, bl1);
#pragma unroll
                for (int mf=0; mf<4; mf++){
                    mma_tf32(acc[mf][nf], ah[mf], bh0, bh1);  // hi*hi
                    mma_tf32(acc[mf][nf], ah[mf], bl0, bl1);  // hi*lo
                    mma_tf32(acc[mf][nf], al[mf], bh0, bh1);  // lo*hi
                }
            }
        }
        __syncthreads();
    }

    // epilogue: c0:(r,2c) c1:(r,2c+1) c2:(r+8,2c) c3:(r+8,2c+1)
#pragma unroll
    for (int mf=0; mf<4; mf++){
        const int row_lo = m0 + wm*64 + mf*16 + lr;
        const int row_hi = row_lo + 8;
#pragma unroll
        for (int nf=0; nf<4; nf++){
            const int col = n0 + wn*32 + nf*8 + lc*2;
            const float2 bb = *(const float2*)&bias[col];
            if (row_lo < M){
                float2 r;
                r.x = acc[mf][nf][0] + bb.x;
                r.y = acc[mf][nf][1] + bb.y;
                if (ACT == 1){ r.x = tanhf(r.x); r.y = tanhf(r.y); }
                *(float2*)&C[(size_t)row_lo*N + col] = r;
            }
            if (row_hi < M){
                float2 r;
                r.x = acc[mf][nf][2] + bb.x;
                r.y = acc[mf][nf][3] + bb.y;
                if (ACT == 1){ r.x = tanhf(r.x); r.y = tanhf(r.y); }
                *(float2*)&C[(size_t)row_hi*N + col] = r;
            }
        }
    }
}

// ---------------- LSTM step: split-K GEMM partials (FFMA2) ----------------
__global__ void __launch_bounds__(64) lstm_gemm(const float* __restrict__ Whh, int hsrc){
    __shared__ float4 Wt4[64*32];   // [row][k4 ^ (row>>2)]
    __shared__ float4 Ht4[16*32];   // [b][k4 ^ (b>>2)]
    const int rt = blockIdx.x, kc = blockIdx.y;
    const int row0 = rt*64, k0 = kc*128;
    const int t = threadIdx.x;
    const float* hp = g_h[hsrc];

    for (int idx = t; idx < 64*32; idx += 64){
        int r = idx >> 5, c4 = idx & 31;
        float4 v = *(const float4*)(Whh + (size_t)(row0 + r)*HH + k0 + c4*4);
        Wt4[r*32 + (c4 ^ (r >> 2))] = v;
    }
    for (int idx = t; idx < 16*32; idx += 64){
        int b = idx >> 5, c4 = idx & 31;
        Ht4[b*32 + (c4 ^ (b >> 2))] = *(const float4*)(hp + b*HH + k0 + c4*4);
    }
    __syncthreads();

    const int tr = t & 15;   // row group (4 rows)
    const int tb = t >> 4;   // b group (4 b)
    u64 acc2[4][2];          // [row][b-pair]
    const u64 z2 = pk2(0.f, 0.f);
#pragma unroll
    for (int i=0;i<4;i++){ acc2[i][0] = z2; acc2[i][1] = z2; }

#pragma unroll 2
    for (int k4 = 0; k4 < 32; k4++){
        float4 w[4], h[4];
#pragma unroll
        for (int i=0;i<4;i++) w[i] = Wt4[(tr*4+i)*32 + (k4 ^ tr)];
#pragma unroll
        for (int j=0;j<4;j++) h[j] = Ht4[(tb*4+j)*32 + (k4 ^ tb)];
        u64 hx0 = pk2(h[0].x, h[1].x), hx1 = pk2(h[2].x, h[3].x);
        u64 hy0 = pk2(h[0].y, h[1].y), hy1 = pk2(h[2].y, h[3].y);
        u64 hz0 = pk2(h[0].z, h[1].z), hz1 = pk2(h[2].z, h[3].z);
        u64 hw0 = pk2(h[0].w, h[1].w), hw1 = pk2(h[2].w, h[3].w);
#pragma unroll
        for (int i=0;i<4;i++){
            u64 px = pk2(w[i].x, w[i].x);
            fma2(acc2[i][0], px, hx0); fma2(acc2[i][1], px, hx1);
            u64 py = pk2(w[i].y, w[i].y);
            fma2(acc2[i][0], py, hy0); fma2(acc2[i][1], py, hy1);
            u64 pz = pk2(w[i].z, w[i].z);
            fma2(acc2[i][0], pz, hz0); fma2(acc2[i][1], pz, hz1);
            u64 pw = pk2(w[i].w, w[i].w);
            fma2(acc2[i][0], pw, hw0); fma2(acc2[i][1], pw, hw1);
        }
    }

#pragma unroll
    for (int i=0;i<4;i++){
        int row = row0 + tr*4 + i;
        float2 p0 = up2(acc2[i][0]);
        float2 p1 = up2(acc2[i][1]);
        g_partial[(size_t)(kc*BB + tb*4 + 0)*G4 + row] = p0.x;
        g_partial[(size_t)(kc*BB + tb*4 + 1)*G4 + row] = p0.y;
        g_partial[(size_t)(kc*BB + tb*4 + 2)*G4 + row] = p1.x;
        g_partial[(size_t)(kc*BB + tb*4 + 3)*G4 + row] = p1.y;
    }
}

__global__ void __launch_bounds__(256) lstm_update(int t, int hdst){
    int tid = blockIdx.x*256 + threadIdx.x;     // 16384 = B*H
    int b = tid >> 10, j = tid & 1023;
    size_t xbase = ((size_t)(b*TT + t))*G4 + j;
    float g0 = g_xg[xbase];
    float g1 = g_xg[xbase + HH];
    float g2 = g_xg[xbase + 2*HH];
    float g3 = g_xg[xbase + 3*HH];
#pragma unroll
    for (int kc=0; kc<8; kc++){
        const float* p = g_partial + (size_t)(kc*BB + b)*G4 + j;
        g0 += p[0]; g1 += p[HH]; g2 += p[2*HH]; g3 += p[3*HH];
    }
    float i_ = 1.f/(1.f+expf(-g0));
    float f_ = 1.f/(1.f+expf(-g1));
    float gc = tanhf(g2);
    float o_ = 1.f/(1.f+expf(-g3));
    float c  = f_*g_c[tid] + i_*gc;
    g_c[tid] = c;
    float h  = o_*tanhf(c);
    g_h[hdst][tid] = h;
    g_hs[((size_t)(b*TT + t))*HH + j] = h;
}

// ---------------- attention: one block per (b,t) --------------------------
__global__ void __launch_bounds__(256) attention_k(){
    __shared__ float4 qs4[256];        // q row (1024 floats)
    __shared__ float sc[56];
    const int bt = blockIdx.x;
    const int b = bt >> 7;             // T=128
    const int t = threadIdx.x;

    qs4[t] = ((const float4*)(g_q + (size_t)bt*HH))[t];
    __syncthreads();

    const int wid = t >> 5, lane = t & 31;
    for (int l = wid; l < CLL; l += 8){
        const float4* kr = (const float4*)(g_k + (size_t)(b*CLL + l)*HH);
        float s = 0.f;
        for (int kk = lane; kk < 256; kk += 32){
            float4 kv = kr[kk];
            float4 qv = qs4[kk];
            s += kv.x*qv.x + kv.y*qv.y + kv.z*qv.z + kv.w*qv.w;
        }
#pragma unroll
        for (int off=16; off; off>>=1) s += __shfl_xor_sync(0xffffffffu, s, off);
        if (lane == 0) sc[l] = s * 0.03125f;   // 1/sqrt(1024)
    }
    __syncthreads();
    if (t == 0){
        float mx = -1e30f;
        for (int l=0;l<CLL;l++) mx = fmaxf(mx, sc[l]);
        float sum = 0.f;
        for (int l=0;l<CLL;l++){ float e = expf(sc[l]-mx); sc[l] = e; sum += e; }
        float inv = 1.f/sum;
        for (int l=0;l<CLL;l++) sc[l] *= inv;
    }
    __syncthreads();

    float4 acc = make_float4(0.f,0.f,0.f,0.f);
    const float4* vb = (const float4*)(g_v + (size_t)b*CLL*HH);
    for (int l=0;l<CLL;l++){
        float p = sc[l];
        float4 vv = vb[l*256 + t];
        acc.x = fmaf(p, vv.x, acc.x);
        acc.y = fmaf(p, vv.y, acc.y);
        acc.z = fmaf(p, vv.z, acc.z);
        acc.w = fmaf(p, vv.w, acc.w);
    }
    ((float4*)(g_att + (size_t)bt*HH))[t] = acc;
}

__global__ void __launch_bounds__(256) concat_k(){
    int row = blockIdx.x;
    int i = threadIdx.x;   // 256
    const float4* a = (const float4*)(g_att + (size_t)row*HH);
    const float4* h = (const float4*)(g_hs + (size_t)row*HH);
    float4* o = (float4*)(g_cat + (size_t)row*2*HH);
    o[i]       = a[i];
    o[256 + i] = h[i];
}

__global__ void __launch_bounds__(256) tail_k(float* __restrict__ out){
    int i = blockIdx.x*256 + threadIdx.x;          // 32768
    const size_t base = (size_t)BT * VV;           // 65,536,000
    if (i < BB*HH) out[base + i] = g_h[0][i];
    else           out[base + i] = g_c[i - BB*HH];
}

// ---------------- launch ---------------------------------------------------
extern "C" void kernel_launch(void* const* d_in, const int* in_sizes, int n_in,
                              void* d_out, int out_size)
{
    const int*   words = (const int*)  d_in[0];
    const float* h0    = (const float*)d_in[1];
    const float* c0    = (const float*)d_in[2];
    const float* ctx   = (const float*)d_in[3];
    const float* emb   = (const float*)d_in[4];
    const float* W_ih  = (const float*)d_in[5];
    const float* W_hh  = (const float*)d_in[6];
    const float* b_ih  = (const float*)d_in[7];
    const float* b_hh  = (const float*)d_in[8];
    const float* Wq    = (const float*)d_in[9];
    const float* bq    = (const float*)d_in[10];
    const float* Wk    = (const float*)d_in[11];
    const float* bk    = (const float*)d_in[12];
    const float* Wv    = (const float*)d_in[13];
    const float* bv    = (const float*)d_in[14];
    const float* Wo    = (const float*)d_in[15];
    const float* bo    = (const float*)d_in[16];
    const float* Wp    = (const float*)d_in[17];
    const float* bp    = (const float*)d_in[18];
    float* out = (float*)d_out;

    // scratch symbol addresses (capture-safe queries, no allocation)
    float *p_xemb, *p_xg, *p_bias, *p_h, *p_c, *p_hs, *p_q, *p_k, *p_v, *p_att, *p_cat, *p_merged;
    cudaGetSymbolAddress((void**)&p_xemb,   g_xemb);
    cudaGetSymbolAddress((void**)&p_xg,     g_xg);
    cudaGetSymbolAddress((void**)&p_bias,   g_bias4h);
    cudaGetSymbolAddress((void**)&p_h,      g_h);
    cudaGetSymbolAddress((void**)&p_c,      g_c);
    cudaGetSymbolAddress((void**)&p_hs,     g_hs);
    cudaGetSymbolAddress((void**)&p_q,      g_q);
    cudaGetSymbolAddress((void**)&p_k,      g_k);
    cudaGetSymbolAddress((void**)&p_v,      g_v);
    cudaGetSymbolAddress((void**)&p_att,    g_att);
    cudaGetSymbolAddress((void**)&p_cat,    g_cat);
    cudaGetSymbolAddress((void**)&p_merged, g_merged);

    // init h, c
    cudaMemcpyAsync(p_h, h0, (size_t)BB*HH*sizeof(float), cudaMemcpyDeviceToDevice, 0);
    cudaMemcpyAsync(p_c, c0, (size_t)BB*HH*sizeof(float), cudaMemcpyDeviceToDevice, 0);

    bias_comb_k<<<16, 256>>>(b_ih, b_hh);
    embed_k<<<BT, 128>>>(words, emb);

    // xg = x_emb @ W_ih^T + (b_ih + b_hh):  [2048,512] x [4096,512]^T
    // grid = (M-tiles, N-tiles): consecutive blocks share a B n-tile (L2 reuse)
    gemm_tf32<0><<<dim3(BT/128, G4/128), 256>>>(p_xemb, W_ih, p_bias, p_xg, BT, G4, EE);

    // LSTM recurrence
    for (int t = 0; t < TT; t++){
        lstm_gemm<<<dim3(64, 8), 64>>>(W_hh, t & 1);
        lstm_update<<<64, 256>>>(t, (t + 1) & 1);
    }

    // q = hs @ Wq^T + bq : [2048,1024] x [1024,1024]^T
    gemm_tf32<0><<<dim3(BT/128, HH/128), 256>>>(p_hs, Wq, bq, p_q, BT, HH, HH);
    // k = ctx @ Wk^T + bk : [784,2048] x [1024,2048]^T
    gemm_tf32<0><<<dim3((BB*CLL + 127)/128, HH/128), 256>>>(ctx, Wk, bk, p_k, BB*CLL, HH, CDD);
    // v = ctx @ Wv^T + bv
    gemm_tf32<0><<<dim3((BB*CLL + 127)/128, HH/128), 256>>>(ctx, Wv, bv, p_v, BB*CLL, HH, CDD);

    attention_k<<<BT, 256>>>();
    concat_k<<<BT, 256>>>();

    // merged = tanh(cat @ Wo^T + bo) : [2048,2048] x [1024,2048]^T
    gemm_tf32<1><<<dim3(BT/128, HH/128), 256>>>(p_cat, Wo, bo, p_merged, BT, HH, 2*HH);

    // logit = merged @ Wp^T + bp : [2048,1024] x [32000,1024]^T -> d_out
    // 16 consecutive m-tile blocks share each 512KB Wp n-tile -> L2-resident
    gemm_tf32<0><<<dim3(BT/128, VV/128), 256>>>(p_merged, Wp, bp, out, BT, VV, HH);

    // h1, c1 tail
    tail_k<<<128, 256>>>(out);
}

// round 12
// speedup vs baseline: 1.1190x; 1.1190x over previous
#include <cuda_runtime.h>
#include <cuda_bf16.h>
#include <math.h>
#include <stdint.h>

// Problem dims
#define BB 16
#define TT 128
#define EE 512
#define HH 1024
#define VV 32000
#define CLL 49
#define CDD 2048
#define BT (BB*TT)            // 2048
#define G4 (4*HH)             // 4096

// persistent LSTM config
#define NBLK 128              // blocks (<=148 SMs, 1 block/SM -> all resident)
#define NTHR 256
#define SW   1088             // smem row stride in floats (1024 + 16 segs * 4 skew)
#define SKW(k) ((k) + (((k) >> 6) << 2))
// smem float offsets
#define WS_OFF 0
#define HS_OFF (32*SW)                 // 34816
#define GS_OFF (HS_OFF + 16*SW)        // 52224
#define CS_OFF (GS_OFF + 512)          // 52736
#define SM_FLOATS (CS_OFF + 128)       // 52864 -> 211456 bytes

typedef unsigned long long u64;
typedef longlong2 ll2;

// ---- packed fp32x2 helpers --------------------------------------------------
__device__ __forceinline__ u64 pk2(float lo, float hi){
    u64 r;
    asm("mov.b64 %0, {%1, %2};" : "=l"(r) : "f"(lo), "f"(hi));
    return r;
}
__device__ __forceinline__ void fma2(u64& d, u64 a, u64 b){
    asm("fma.rn.f32x2 %0, %1, %2, %3;" : "=l"(d) : "l"(a), "l"(b), "l"(d));
}
__device__ __forceinline__ u64 add2(u64 a, u64 b){
    u64 r;
    asm("add.rn.f32x2 %0, %1, %2;" : "=l"(r) : "l"(a), "l"(b));
    return r;
}
__device__ __forceinline__ float2 up2(u64 v){
    float2 r;
    asm("mov.b64 {%0, %1}, %2;" : "=f"(r.x), "=f"(r.y) : "l"(v));
    return r;
}

// ---- tf32 helpers -----------------------------------------------------------
__device__ __forceinline__ void split_tf(float x, uint32_t& hi, uint32_t& lo){
    asm("cvt.rna.tf32.f32 %0, %1;" : "=r"(hi) : "f"(x));
    float r = x - __uint_as_float(hi);
    asm("cvt.rna.tf32.f32 %0, %1;" : "=r"(lo) : "f"(r));
}
__device__ __forceinline__ void mma_tf32(float* c, const uint32_t* a, uint32_t b0, uint32_t b1){
    asm volatile("mma.sync.aligned.m16n8k8.row.col.f32.tf32.tf32.f32 "
        "{%0,%1,%2,%3}, {%4,%5,%6,%7}, {%8,%9}, {%0,%1,%2,%3};"
        : "+f"(c[0]), "+f"(c[1]), "+f"(c[2]), "+f"(c[3])
        : "r"(a[0]), "r"(a[1]), "r"(a[2]), "r"(a[3]), "r"(b0), "r"(b1));
}

// ---------------- scratch (device globals; no allocation allowed) ----------
__device__ float g_xemb[BT*EE];          // 2048x512
__device__ float g_xg[(size_t)BT*G4];    // 2048x4096
__device__ float g_bias4h[G4];
__device__ float g_hcur[2][BB*HH];       // double-buffered h across steps
__device__ float g_c[BB*HH];
__device__ float g_hs[(size_t)BT*HH];    // 2048x1024 (contiguous A for q GEMM)
__device__ float g_q[(size_t)BT*HH];
__device__ float g_k[(size_t)BB*CLL*HH];
__device__ float g_v[(size_t)BB*CLL*HH];
__device__ float g_cat[(size_t)BT*2*HH]; // 2048x2048: [att | hs], filled in-place
__device__ float g_merged[(size_t)BT*HH];
// grid barrier state
__device__ unsigned g_barcnt;
__device__ volatile unsigned g_bargen;

// ---------------- small kernels -------------------------------------------
__global__ void bias_comb_k(const float* __restrict__ a, const float* __restrict__ b){
    int i = blockIdx.x*256 + threadIdx.x;
    if (i == 0){ g_barcnt = 0; g_bargen = 0; }
    if (i < G4) g_bias4h[i] = a[i] + b[i];
}

__global__ void embed_k(const int* __restrict__ words, const float* __restrict__ emb){
    int row = blockIdx.x;                 // 0..2047
    int w = words[row];
    const float4* src = (const float4*)(emb + (size_t)w*EE);
    float4* dst = (float4*)(g_xemb + (size_t)row*EE);
    dst[threadIdx.x] = src[threadIdx.x];  // 128 threads * float4 = 512 floats
}

// ---------------- tensor-core GEMM (3xTF32): C = A[M,K] @ B[N,K]^T + bias --
// BM=BN=128, BK=16, 256 threads (8 warps, 2Mx4N), warp tile 64x32.
// Grid: (M-tiles, N-tiles) -> consecutive blocks share a B n-tile (L2 reuse).
template<int ACT>
__global__ void __launch_bounds__(256) gemm_tf32(
    const float* __restrict__ A, const float* __restrict__ B,
    const float* __restrict__ bias, float* __restrict__ C,
    int M, int N, int K)
{
    __shared__ float As[128][20];   // stride 20 floats = 80B (16B aligned)
    __shared__ float Bs[128][20];
    const int m0 = blockIdx.x*128, n0 = blockIdx.y*128;
    const int t = threadIdx.x;
    const int warp = t >> 5, lane = t & 31;
    const int wm = warp & 1;
    const int wn = warp >> 1;
    const int lr = lane >> 2, lc = lane & 3;

    const int r0 = t >> 2, c4 = (t & 3)*4;
    const bool av0 = (m0 + r0) < M;
    const bool av1 = (m0 + 64 + r0) < M;
    const float* Ap0 = A + (size_t)(m0 + r0)*K + c4;
    const float* Ap1 = A + (size_t)(m0 + 64 + r0)*K + c4;
    const float* Bp0 = B + (size_t)(n0 + r0)*K + c4;
    const float* Bp1 = B + (size_t)(n0 + 64 + r0)*K + c4;

    float acc[4][4][4];
#pragma unroll
    for (int i=0;i<4;i++)
#pragma unroll
        for (int j=0;j<4;j++)
#pragma unroll
            for (int r=0;r<4;r++) acc[i][j][r] = 0.f;

    const int nk = K >> 4;
    const float4 z4 = make_float4(0.f,0.f,0.f,0.f);
    float4 a0v = av0 ? *(const float4*)Ap0 : z4;
    float4 a1v = av1 ? *(const float4*)Ap1 : z4;
    float4 b0v = *(const float4*)Bp0;
    float4 b1v = *(const float4*)Bp1;

    for (int kt=0; kt<nk; kt++){
        *(float4*)&As[r0][c4]      = a0v;
        *(float4*)&As[64 + r0][c4] = a1v;
        *(float4*)&Bs[r0][c4]      = b0v;
        *(float4*)&Bs[64 + r0][c4] = b1v;
        __syncthreads();

        if (kt + 1 < nk){
            Ap0 += 16; Ap1 += 16; Bp0 += 16; Bp1 += 16;
            a0v = av0 ? *(const float4*)Ap0 : z4;
            a1v = av1 ? *(const float4*)Ap1 : z4;
            b0v = *(const float4*)Bp0;
            b1v = *(const float4*)Bp1;
        }

#pragma unroll
        for (int s=0; s<2; s++){
            const int k0 = s*8;
            uint32_t ah[4][4], al[4][4];
#pragma unroll
            for (int mf=0; mf<4; mf++){
                const int mr = wm*64 + mf*16 + lr;
                split_tf(As[mr  ][k0+lc  ], ah[mf][0], al[mf][0]);
                split_tf(As[mr+8][k0+lc  ], ah[mf][1], al[mf][1]);
                split_tf(As[mr  ][k0+lc+4], ah[mf][2], al[mf][2]);
                split_tf(As[mr+8][k0+lc+4], ah[mf][3], al[mf][3]);
            }
#pragma unroll
            for (int nf=0; nf<4; nf++){
                const int nr = wn*32 + nf*8 + lr;
                uint32_t bh0, bl0, bh1, bl1;
                split_tf(Bs[nr][k0+lc  ], bh0, bl0);
                split_tf(Bs[nr][k0+lc+4], bh1, bl1);
#pragma unroll
                for (int mf=0; mf<4; mf++){
                    mma_tf32(acc[mf][nf], ah[mf], bh0, bh1);
                    mma_tf32(acc[mf][nf], ah[mf], bl0, bl1);
                    mma_tf32(acc[mf][nf], al[mf], bh0, bh1);
                }
            }
        }
        __syncthreads();
    }

#pragma unroll
    for (int mf=0; mf<4; mf++){
        const int row_lo = m0 + wm*64 + mf*16 + lr;
        const int row_hi = row_lo + 8;
#pragma unroll
        for (int nf=0; nf<4; nf++){
            const int col = n0 + wn*32 + nf*8 + lc*2;
            const float2 bb = *(const float2*)&bias[col];
            if (row_lo < M){
                float2 r;
                r.x = acc[mf][nf][0] + bb.x;
                r.y = acc[mf][nf][1] + bb.y;
                if (ACT == 1){ r.x = tanhf(r.x); r.y = tanhf(r.y); }
                *(float2*)&C[(size_t)row_lo*N + col] = r;
            }
            if (row_hi < M){
                float2 r;
                r.x = acc[mf][nf][2] + bb.x;
                r.y = acc[mf][nf][3] + bb.y;
                if (ACT == 1){ r.x = tanhf(r.x); r.y = tanhf(r.y); }
                *(float2*)&C[(size_t)row_hi*N + col] = r;
            }
        }
    }
}

// ---------------- persistent LSTM over all 128 steps ------------------------
// 128 blocks x 256 threads. Block r owns hidden units [8r, 8r+8): its 32 W_hh
// rows (4 gates x 8 units) live in smem for the whole kernel. One grid barrier
// per step; h double-buffered in gmem by step parity; c stays in smem.
__device__ __forceinline__ void grid_bar(unsigned want){
    __syncthreads();
    if (threadIdx.x == 0){
        __threadfence();
        unsigned a = atomicAdd(&g_barcnt, 1);
        if (a == NBLK - 1){
            g_barcnt = 0;
            __threadfence();
            g_bargen = want;
        } else {
            while (g_bargen != want) { }
        }
        __threadfence();
    }
    __syncthreads();
}

__global__ void __launch_bounds__(NTHR, 1) lstm_persist(
    const float* __restrict__ Whh, const float* __restrict__ c0)
{
    extern __shared__ float sm[];
    float* Ws = sm + WS_OFF;
    float* Hs = sm + HS_OFF;
    float* gS = sm + GS_OFF;
    float* cS = sm + CS_OFF;

    const int tid = threadIdx.x;
    const int u0  = blockIdx.x * 8;

    // stage W slice: local row lr = gate*8+uu -> global row gate*1024 + u0+uu
    for (int i = tid; i < 32*256; i += NTHR){
        int lr  = i >> 8;
        int c4f = (i & 255) << 2;
        int gr  = (lr >> 3)*HH + u0 + (lr & 7);
        *(float4*)(Ws + lr*SW + SKW(c4f)) = *(const float4*)(Whh + (size_t)gr*HH + c4f);
    }
    // stage c slice
    if (tid < 128){
        int uu = tid >> 4, b = tid & 15;
        cS[tid] = c0[b*HH + u0 + uu];
    }

    const int kseg = tid & 15, pos = tid >> 4;
    const int rt = pos & 3, bt = pos >> 2;
    const float* Wsb = Ws + (rt*8)*SW;
    const float* Hsb = Hs + (bt*4)*SW;
    const int koff0 = kseg*68;

    for (int t = 0; t < TT; t++){
        const int rbuf = t & 1, wbuf = (t + 1) & 1;
        // stage h(t) into smem
        const float* hsrc = g_hcur[rbuf];
        __syncthreads();   // protect Hs from previous step's readers
        for (int i = tid; i < 16*256; i += NTHR){
            int b   = i >> 8;
            int c4f = (i & 255) << 2;
            *(float4*)(Hs + b*SW + SKW(c4f)) = *(const float4*)(hsrc + b*HH + c4f);
        }
        __syncthreads();

        // gemm: 8 rows x 4 b per thread over 64 k's, FFMA2 packed along k
        u64 acc[8][4];
#pragma unroll
        for (int i=0;i<8;i++)
#pragma unroll
            for (int j=0;j<4;j++) acc[i][j] = 0ull;

#pragma unroll 4
        for (int it = 0; it < 16; it++){
            const int ko = koff0 + it*4;
            ll2 h0v = *(const ll2*)(Hsb + 0*SW + ko);
            ll2 h1v = *(const ll2*)(Hsb + 1*SW + ko);
            ll2 h2v = *(const ll2*)(Hsb + 2*SW + ko);
            ll2 h3v = *(const ll2*)(Hsb + 3*SW + ko);
#pragma unroll
            for (int i=0;i<8;i++){
                ll2 wv = *(const ll2*)(Wsb + i*SW + ko);
                fma2(acc[i][0], (u64)wv.x, (u64)h0v.x);
                fma2(acc[i][0], (u64)wv.y, (u64)h0v.y);
                fma2(acc[i][1], (u64)wv.x, (u64)h1v.x);
                fma2(acc[i][1], (u64)wv.y, (u64)h1v.y);
                fma2(acc[i][2], (u64)wv.x, (u64)h2v.x);
                fma2(acc[i][2], (u64)wv.y, (u64)h2v.y);
                fma2(acc[i][3], (u64)wv.x, (u64)h3v.x);
                fma2(acc[i][3], (u64)wv.y, (u64)h3v.y);
            }
        }

        // reduce over 16 ksegs (lanes 0-15 / 16-31 of each warp)
#pragma unroll
        for (int i=0;i<8;i++)
#pragma unroll
            for (int j=0;j<4;j++){
                u64 a = acc[i][j];
                a = add2(a, __shfl_xor_sync(0xffffffffu, a, 1));
                a = add2(a, __shfl_xor_sync(0xffffffffu, a, 2));
                a = add2(a, __shfl_xor_sync(0xffffffffu, a, 4));
                a = add2(a, __shfl_xor_sync(0xffffffffu, a, 8));
                acc[i][j] = a;
            }
        if (kseg == 0){
#pragma unroll
            for (int i=0;i<8;i++)
#pragma unroll
                for (int j=0;j<4;j++){
                    float2 p = up2(acc[i][j]);
                    gS[(rt*8 + i)*16 + bt*4 + j] = p.x + p.y;
                }
        }
        __syncthreads();

        // local gate->h,c update for owned units
        if (tid < 128){
            int uu = tid >> 4, b = tid & 15;
            size_t xb = ((size_t)(b*TT + t))*G4 + u0 + uu;
            float gi = gS[(0*8 + uu)*16 + b] + g_xg[xb];
            float gf = gS[(1*8 + uu)*16 + b] + g_xg[xb + HH];
            float gg = gS[(2*8 + uu)*16 + b] + g_xg[xb + 2*HH];
            float go = gS[(3*8 + uu)*16 + b] + g_xg[xb + 3*HH];
            float i_ = 1.f/(1.f + expf(-gi));
            float f_ = 1.f/(1.f + expf(-gf));
            float gc = tanhf(gg);
            float o_ = 1.f/(1.f + expf(-go));
            float c  = f_*cS[tid] + i_*gc;
            cS[tid] = c;
            float h = o_*tanhf(c);
            g_hcur[wbuf][b*HH + u0 + uu] = h;
            size_t row = (size_t)(b*TT + t);
            g_hs[row*HH + u0 + uu] = h;                    // contiguous (q GEMM A)
            g_cat[row*2*HH + HH + u0 + uu] = h;            // cat second half (fused concat)
        }
        grid_bar((unsigned)(t + 1));
    }

    // final c for tail
    if (tid < 128){
        int uu = tid >> 4, b = tid & 15;
        g_c[b*HH + u0 + uu] = cS[tid];
    }
}

// ---------------- attention: one block per (b,t) --------------------------
// writes att directly into g_cat first half (concat fused away)
__global__ void __launch_bounds__(256) attention_k(){
    __shared__ float4 qs4[256];
    __shared__ float sc[56];
    const int bt = blockIdx.x;
    const int b = bt >> 7;
    const int t = threadIdx.x;

    qs4[t] = ((const float4*)(g_q + (size_t)bt*HH))[t];
    __syncthreads();

    const int wid = t >> 5, lane = t & 31;
    for (int l = wid; l < CLL; l += 8){
        const float4* kr = (const float4*)(g_k + (size_t)(b*CLL + l)*HH);
        float s = 0.f;
        for (int kk = lane; kk < 256; kk += 32){
            float4 kv = kr[kk];
            float4 qv = qs4[kk];
            s += kv.x*qv.x + kv.y*qv.y + kv.z*qv.z + kv.w*qv.w;
        }
#pragma unroll
        for (int off=16; off; off>>=1) s += __shfl_xor_sync(0xffffffffu, s, off);
        if (lane == 0) sc[l] = s * 0.03125f;
    }
    __syncthreads();
    if (t == 0){
        float mx = -1e30f;
        for (int l=0;l<CLL;l++) mx = fmaxf(mx, sc[l]);
        float sum = 0.f;
        for (int l=0;l<CLL;l++){ float e = expf(sc[l]-mx); sc[l] = e; sum += e; }
        float inv = 1.f/sum;
        for (int l=0;l<CLL;l++) sc[l] *= inv;
    }
    __syncthreads();

    float4 acc = make_float4(0.f,0.f,0.f,0.f);
    const float4* vb = (const float4*)(g_v + (size_t)b*CLL*HH);
    for (int l=0;l<CLL;l++){
        float p = sc[l];
        float4 vv = vb[l*256 + t];
        acc.x = fmaf(p, vv.x, acc.x);
        acc.y = fmaf(p, vv.y, acc.y);
        acc.z = fmaf(p, vv.z, acc.z);
        acc.w = fmaf(p, vv.w, acc.w);
    }
    ((float4*)(g_cat + (size_t)bt*2*HH))[t] = acc;   // first half of cat row
}

__global__ void __launch_bounds__(256) tail_k(float* __restrict__ out){
    int i = blockIdx.x*256 + threadIdx.x;          // 32768
    const size_t base = (size_t)BT * VV;
    if (i < BB*HH) out[base + i] = g_hcur[0][i];   // h(128) lives in buffer 0
    else           out[base + i] = g_c[i - BB*HH];
}

// ---------------- launch ---------------------------------------------------
extern "C" void kernel_launch(void* const* d_in, const int* in_sizes, int n_in,
                              void* d_out, int out_size)
{
    const int*   words = (const int*)  d_in[0];
    const float* h0    = (const float*)d_in[1];
    const float* c0    = (const float*)d_in[2];
    const float* ctx   = (const float*)d_in[3];
    const float* emb   = (const float*)d_in[4];
    const float* W_ih  = (const float*)d_in[5];
    const float* W_hh  = (const float*)d_in[6];
    const float* b_ih  = (const float*)d_in[7];
    const float* b_hh  = (const float*)d_in[8];
    const float* Wq    = (const float*)d_in[9];
    const float* bq    = (const float*)d_in[10];
    const float* Wk    = (const float*)d_in[11];
    const float* bk    = (const float*)d_in[12];
    const float* Wv    = (const float*)d_in[13];
    const float* bv    = (const float*)d_in[14];
    const float* Wo    = (const float*)d_in[15];
    const float* bo    = (const float*)d_in[16];
    const float* Wp    = (const float*)d_in[17];
    const float* bp    = (const float*)d_in[18];
    float* out = (float*)d_out;

    float *p_xemb, *p_xg, *p_bias, *p_hcur, *p_hs, *p_q, *p_k, *p_v, *p_cat, *p_merged;
    cudaGetSymbolAddress((void**)&p_xemb,   g_xemb);
    cudaGetSymbolAddress((void**)&p_xg,     g_xg);
    cudaGetSymbolAddress((void**)&p_bias,   g_bias4h);
    cudaGetSymbolAddress((void**)&p_hcur,   g_hcur);
    cudaGetSymbolAddress((void**)&p_hs,     g_hs);
    cudaGetSymbolAddress((void**)&p_q,      g_q);
    cudaGetSymbolAddress((void**)&p_k,      g_k);
    cudaGetSymbolAddress((void**)&p_v,      g_v);
    cudaGetSymbolAddress((void**)&p_cat,    g_cat);
    cudaGetSymbolAddress((void**)&p_merged, g_merged);

    // unconditional (idempotent, host-side, capture-safe) — no static guards
    cudaFuncSetAttribute(lstm_persist, cudaFuncAttributeMaxDynamicSharedMemorySize,
                         SM_FLOATS*4);

    // h(0) into buffer 0 (re-copied every launch/replay)
    cudaMemcpyAsync(p_hcur, h0, (size_t)BB*HH*sizeof(float), cudaMemcpyDeviceToDevice, 0);

    bias_comb_k<<<16, 256>>>(b_ih, b_hh);
    embed_k<<<BT, 128>>>(words, emb);

    // xg = x_emb @ W_ih^T + (b_ih + b_hh)
    gemm_tf32<0><<<dim3(BT/128, G4/128), 256>>>(p_xemb, W_ih, p_bias, p_xg, BT, G4, EE);

    // whole recurrence in one persistent kernel (also fills cat second half)
    lstm_persist<<<NBLK, NTHR, SM_FLOATS*4>>>(W_hh, c0);

    // q = hs @ Wq^T + bq
    gemm_tf32<0><<<dim3(BT/128, HH/128), 256>>>(p_hs, Wq, bq, p_q, BT, HH, HH);
    // k = ctx @ Wk^T + bk
    gemm_tf32<0><<<dim3((BB*CLL + 127)/128, HH/128), 256>>>(ctx, Wk, bk, p_k, BB*CLL, HH, CDD);
    // v = ctx @ Wv^T + bv
    gemm_tf32<0><<<dim3((BB*CLL + 127)/128, HH/128), 256>>>(ctx, Wv, bv, p_v, BB*CLL, HH, CDD);

    attention_k<<<BT, 256>>>();   // writes att into cat first half

    // merged = tanh(cat @ Wo^T + bo)
    gemm_tf32<1><<<dim3(BT/128, HH/128), 256>>>(p_cat, Wo, bo, p_merged, BT, HH, 2*HH);

    // logit = merged @ Wp^T + bp
    gemm_tf32<0><<<dim3(BT/128, VV/128), 256>>>(p_merged, Wp, bp, out, BT, VV, HH);

    tail_k<<<128, 256>>>(out);
}